// round 3
// baseline (speedup 1.0000x reference)
#include <cuda_runtime.h>
#include <cstdint>
#include <cstddef>

// ---------------------------------------------------------------------------
// CustomBLIP:
//   img = normalize(image_embeds @ Wi^T + bi); txt = normalize(text_embeds @ Wt^T + bt)
//   feats[b,k] = relu( sum_{i,j} img[b,i]*txt[b,j]*Wp[k,i,j] + bp[k] )
//   out[b] = sigmoid( feats[b,:] @ Wc^T + bc )
//
// Stage 1 (map_norm): SIMT fp32 maps + L2 normalize -> g_img, g_txt
// Stage 2 (bilinear): tf32 mma.sync GEMM  D[b,i] = txt @ Wp_k^T  (K=j=512),
//   epilogue-fused dot with img -> per-warp partials in g_part. 537MB streamed once.
// Stage 3 (head): sum partials, +bp, relu, @Wc, sigmoid.
// ---------------------------------------------------------------------------

#define B_SZ   256
#define M_DIM  512

__device__ float g_img[B_SZ * M_DIM];
__device__ float g_txt[B_SZ * M_DIM];
__device__ float g_part[512 * 8 * B_SZ];   // [k][slot(ichunk*2+wn)][b]

// ===========================================================================
// Stage 1
// ===========================================================================
__global__ void __launch_bounds__(128) map_norm_kernel(
    const float* __restrict__ img_e, const float* __restrict__ txt_e,
    const float* __restrict__ Wi, const float* __restrict__ bi,
    const float* __restrict__ Wt, const float* __restrict__ bt)
{
    const int mat   = blockIdx.x >> 5;
    const int btile = blockIdx.x & 31;
    const float* X    = mat ? txt_e : img_e;
    const float* W    = mat ? Wt : Wi;
    const float* bias = mat ? bt : bi;
    float* dst        = mat ? g_txt : g_img;
    const int b0 = btile * 8;

    __shared__ float xs[8][512];
    __shared__ float os[8][512];
    const int tid = threadIdx.x;

    {
        const float4* src = (const float4*)(X + (size_t)b0 * 512);
        float4* d4 = (float4*)xs;
        for (int v = tid; v < 1024; v += 128) d4[v] = src[v];
    }
    __syncthreads();

    const int m0 = tid * 4;
    float acc[4][8];
    #pragma unroll
    for (int mi = 0; mi < 4; mi++) {
        float bv = bias[m0 + mi];
        #pragma unroll
        for (int b = 0; b < 8; b++) acc[mi][b] = bv;
    }

    for (int j4 = 0; j4 < 128; ++j4) {
        float4 xv[8];
        #pragma unroll
        for (int b = 0; b < 8; b++) xv[b] = *(const float4*)&xs[b][j4 * 4];
        #pragma unroll
        for (int mi = 0; mi < 4; mi++) {
            float4 wv = *(const float4*)&W[(size_t)(m0 + mi) * 512 + j4 * 4];
            #pragma unroll
            for (int b = 0; b < 8; b++) {
                acc[mi][b] += wv.x * xv[b].x;
                acc[mi][b] += wv.y * xv[b].y;
                acc[mi][b] += wv.z * xv[b].z;
                acc[mi][b] += wv.w * xv[b].w;
            }
        }
    }

    #pragma unroll
    for (int mi = 0; mi < 4; mi++)
        #pragma unroll
        for (int b = 0; b < 8; b++)
            os[b][m0 + mi] = acc[mi][b];
    __syncthreads();

    const int wid = tid >> 5, lane = tid & 31;
    for (int bb = wid; bb < 8; bb += 4) {
        float ss = 0.f;
        for (int j = lane; j < 512; j += 32) { float v = os[bb][j]; ss += v * v; }
        #pragma unroll
        for (int o = 16; o; o >>= 1) ss += __shfl_xor_sync(0xFFFFFFFFu, ss, o);
        float inv = 1.0f / fmaxf(sqrtf(ss), 1e-12f);
        for (int j = lane; j < 512; j += 32)
            dst[(size_t)(b0 + bb) * 512 + j] = os[bb][j] * inv;
    }
}

// ===========================================================================
// Stage 2: tf32 mma.sync bilinear GEMM
// CTA: k = bid>>2, ichunk = bid&3. Tile: M=256 (all batch) x N=128 (i), K=512 (j).
// 8 warps: wm = w>>1 (64 batch rows), wn = w&1 (64 i cols). Warp tile 64x64.
// ===========================================================================

__device__ __forceinline__ uint32_t smem_u32(const void* p) {
    uint32_t a;
    asm("{ .reg .u64 t; cvta.to.shared.u64 t, %1; cvt.u32.u64 %0, t; }"
        : "=r"(a) : "l"(p));
    return a;
}

__device__ __forceinline__ void cp16(uint32_t dst, const void* src) {
    asm volatile("cp.async.cg.shared.global [%0], [%1], 16;" :: "r"(dst), "l"(src));
}

__device__ __forceinline__ uint32_t ld_tf32(const float* p) {
    uint32_t u;
    asm("cvt.rna.tf32.f32 %0, %1;" : "=r"(u) : "f"(*p));
    return u;
}

#define PAD 36              // floats per SMEM row (32 data + 4 pad)
#define TXT_STAGE (256 * PAD)
#define WP_STAGE  (128 * PAD)
#define K2_SMEM   ((2 * TXT_STAGE + 2 * WP_STAGE) * 4)   // 110592 B

__global__ void __launch_bounds__(256, 1) bilinear_kernel(const float* __restrict__ Wp)
{
    extern __shared__ __align__(16) float dsm[];
    float* txt_s = dsm;                      // [2][256][PAD]
    float* wp_s  = dsm + 2 * TXT_STAGE;      // [2][128][PAD]

    const int tid  = threadIdx.x;
    const int w    = tid >> 5;
    const int lane = tid & 31;
    const int wm   = w >> 1;       // 0..3 -> batch rows wm*64
    const int wn   = w & 1;        // 0..1 -> i cols wn*64
    const int g    = lane >> 2;    // 0..7
    const int c    = lane & 3;     // 0..3

    const int k      = blockIdx.x >> 2;
    const int ichunk = blockIdx.x & 3;

    const float* wpk = Wp + ((size_t)k << 18) + ((size_t)(ichunk * 128) << 9);

    // ---- async load of one 32-j chunk into stage s ----
    auto load_chunk = [&](int jc, int s) {
        const uint32_t t_base = smem_u32(txt_s + s * TXT_STAGE);
        const uint32_t w_base = smem_u32(wp_s  + s * WP_STAGE);
        const float* tg = g_txt + jc * 32;
        const float* wg = wpk   + jc * 32;
        #pragma unroll
        for (int q = 0; q < 8; q++) {           // txt: 2048 float4
            int idx = tid + 256 * q;
            int row = idx >> 3, c4 = idx & 7;
            cp16(t_base + (uint32_t)(row * PAD + c4 * 4) * 4,
                 tg + ((size_t)row << 9) + c4 * 4);
        }
        #pragma unroll
        for (int q = 0; q < 4; q++) {           // wp: 1024 float4
            int idx = tid + 256 * q;
            int row = idx >> 3, c4 = idx & 7;
            cp16(w_base + (uint32_t)(row * PAD + c4 * 4) * 4,
                 wg + ((size_t)row << 9) + c4 * 4);
        }
        asm volatile("cp.async.commit_group;" ::: "memory");
    };

    float d[4][8][4];
    #pragma unroll
    for (int mt = 0; mt < 4; mt++)
        #pragma unroll
        for (int nt = 0; nt < 8; nt++)
            #pragma unroll
            for (int r = 0; r < 4; r++) d[mt][nt][r] = 0.f;

    load_chunk(0, 0);

    for (int jc = 0; jc < 16; ++jc) {
        if (jc < 15) load_chunk(jc + 1, (jc + 1) & 1);
        if (jc < 15) asm volatile("cp.async.wait_group 1;" ::: "memory");
        else         asm volatile("cp.async.wait_group 0;" ::: "memory");
        __syncthreads();

        const float* ts = txt_s + (jc & 1) * TXT_STAGE;
        const float* ws = wp_s  + (jc & 1) * WP_STAGE;

        #pragma unroll
        for (int ks = 0; ks < 4; ++ks) {
            const int j0 = ks * 8;
            uint32_t a[4][4];
            #pragma unroll
            for (int mt = 0; mt < 4; mt++) {
                const float* tr = ts + (wm * 64 + mt * 16 + g) * PAD + j0 + c;
                a[mt][0] = ld_tf32(tr);
                a[mt][1] = ld_tf32(tr + 8 * PAD);
                a[mt][2] = ld_tf32(tr + 4);
                a[mt][3] = ld_tf32(tr + 8 * PAD + 4);
            }
            uint32_t bf[8][2];
            #pragma unroll
            for (int nt = 0; nt < 8; nt++) {
                const float* wr = ws + (wn * 64 + nt * 8 + g) * PAD + j0 + c;
                bf[nt][0] = ld_tf32(wr);
                bf[nt][1] = ld_tf32(wr + 4);
            }
            #pragma unroll
            for (int mt = 0; mt < 4; mt++)
                #pragma unroll
                for (int nt = 0; nt < 8; nt++) {
                    asm volatile(
                        "mma.sync.aligned.m16n8k8.row.col.f32.tf32.tf32.f32 "
                        "{%0,%1,%2,%3}, {%4,%5,%6,%7}, {%8,%9}, {%0,%1,%2,%3};"
                        : "+f"(d[mt][nt][0]), "+f"(d[mt][nt][1]),
                          "+f"(d[mt][nt][2]), "+f"(d[mt][nt][3])
                        : "r"(a[mt][0]), "r"(a[mt][1]), "r"(a[mt][2]), "r"(a[mt][3]),
                          "r"(bf[nt][0]), "r"(bf[nt][1]));
                }
        }
        __syncthreads();
    }

    // ---- fused epilogue: partial feats = sum_i img[b,i] * D[b,i] ----
    const int slot = ichunk * 2 + wn;
    float* outp = g_part + ((size_t)(k * 8 + slot) << 8);
    const int ibase = ichunk * 128 + wn * 64;

    #pragma unroll
    for (int mt = 0; mt < 4; mt++) {
        const int b_lo = wm * 64 + mt * 16 + g;
        const int b_hi = b_lo + 8;
        float plo = 0.f, phi = 0.f;
        #pragma unroll
        for (int nt = 0; nt < 8; nt++) {
            const int icol = ibase + nt * 8 + 2 * c;
            float2 vlo = *(const float2*)&g_img[((size_t)b_lo << 9) + icol];
            float2 vhi = *(const float2*)&g_img[((size_t)b_hi << 9) + icol];
            plo += d[mt][nt][0] * vlo.x + d[mt][nt][1] * vlo.y;
            phi += d[mt][nt][2] * vhi.x + d[mt][nt][3] * vhi.y;
        }
        plo += __shfl_xor_sync(0xFFFFFFFFu, plo, 1);
        plo += __shfl_xor_sync(0xFFFFFFFFu, plo, 2);
        phi += __shfl_xor_sync(0xFFFFFFFFu, phi, 1);
        phi += __shfl_xor_sync(0xFFFFFFFFu, phi, 2);
        if (c == 0) {
            outp[b_lo] = plo;
            outp[b_hi] = phi;
        }
    }
}

// ===========================================================================
// Stage 3: out[b] = sigmoid( sum_k relu(sum_s part[k][s][b] + bp[k]) * Wc[k] + bc )
// ===========================================================================
__global__ void __launch_bounds__(128) head_kernel(
    const float* __restrict__ bp, const float* __restrict__ Wc,
    const float* __restrict__ bc, float* __restrict__ out)
{
    const int b = blockIdx.x;
    const int t = threadIdx.x;
    float s = 0.f;
    for (int k = t; k < 512; k += 128) {
        float f = bp[k];
        #pragma unroll
        for (int sl = 0; sl < 8; sl++)
            f += g_part[(((size_t)k * 8 + sl) << 8) + b];
        s += fmaxf(f, 0.f) * Wc[k];
    }
    #pragma unroll
    for (int o = 16; o; o >>= 1) s += __shfl_xor_sync(0xFFFFFFFFu, s, o);
    __shared__ float red[4];
    if ((t & 31) == 0) red[t >> 5] = s;
    __syncthreads();
    if (t == 0) {
        float tot = red[0] + red[1] + red[2] + red[3] + bc[0];
        out[b] = 1.f / (1.f + expf(-tot));
    }
}

// ===========================================================================
extern "C" void kernel_launch(void* const* d_in, const int* in_sizes, int n_in,
                              void* d_out, int out_size)
{
    const float* img_e = (const float*)d_in[0];
    const float* txt_e = (const float*)d_in[1];
    const float* Wi    = (const float*)d_in[2];
    const float* bi    = (const float*)d_in[3];
    const float* Wt    = (const float*)d_in[4];
    const float* bt    = (const float*)d_in[5];
    const float* Wp    = (const float*)d_in[6];
    const float* bp    = (const float*)d_in[7];
    const float* Wc    = (const float*)d_in[8];
    const float* bc    = (const float*)d_in[9];
    float* out = (float*)d_out;

    cudaFuncSetAttribute(bilinear_kernel,
                         cudaFuncAttributeMaxDynamicSharedMemorySize, K2_SMEM);

    map_norm_kernel<<<64, 128>>>(img_e, txt_e, Wi, bi, Wt, bt);
    bilinear_kernel<<<2048, 256, K2_SMEM>>>(Wp);
    head_kernel<<<256, 128>>>(bp, Wc, bc, out);
}

// round 5
// speedup vs baseline: 2.5003x; 2.5003x over previous
#include <cuda_runtime.h>
#include <cuda_bf16.h>
#include <cstdint>
#include <cstddef>

// ---------------------------------------------------------------------------
// CustomBLIP:
//   img = normalize(image_embeds @ Wi^T + bi); txt = normalize(text_embeds @ Wt^T + bt)
//   feats[b,k] = relu( sum_{i,j} img[b,i]*txt[b,j]*Wp[k,i,j] + bp[k] )
//   out[b] = sigmoid( feats[b,:] @ Wc^T + bc )
//
// Stage 1: SIMT maps + L2 normalize -> g_img (fp32), g_txt_bf (bf16)
// Stage 2: bf16 mma.sync m16n8k16 GEMM D[b,i] = txt @ Wp_k^T with inline
//          fp32->bf16 conversion of Wp (streamed once, 537MB), epilogue-fused
//          dot with img -> g_part[b][k*4+ichunk]
// Stage 3: sum 4 slots, +bp, relu, @Wc, sigmoid.
// ---------------------------------------------------------------------------

#define B_SZ   256
#define M_DIM  512

__device__ float          g_img[B_SZ * M_DIM];
__device__ __nv_bfloat16  g_txt_bf[B_SZ * M_DIM];
__device__ float          g_part[B_SZ * 2048];    // [b][k*4 + ichunk]

// ===========================================================================
// Stage 1: out = normalize(X @ W^T + b). grid 128: [0,64)=image, [64,128)=text.
// 4 batch rows per block, 256 threads (2 features x 4 rows each).
// ===========================================================================
__global__ void __launch_bounds__(256) map_norm_kernel(
    const float* __restrict__ img_e, const float* __restrict__ txt_e,
    const float* __restrict__ Wi, const float* __restrict__ bi,
    const float* __restrict__ Wt, const float* __restrict__ bt)
{
    const int mat   = blockIdx.x >> 6;
    const int btile = blockIdx.x & 63;
    const float* X    = mat ? txt_e : img_e;
    const float* W    = mat ? Wt : Wi;
    const float* bias = mat ? bt : bi;
    const int b0 = btile * 4;

    __shared__ float xs[4][512];
    __shared__ float os[4][512];
    const int tid = threadIdx.x;

    {
        const float4* src = (const float4*)(X + (size_t)b0 * 512);
        float4* d4 = (float4*)xs;
        #pragma unroll
        for (int v = tid; v < 512; v += 256) d4[v] = src[v];
    }
    __syncthreads();

    const int m0 = tid * 2;
    float acc[2][4];
    #pragma unroll
    for (int mi = 0; mi < 2; mi++) {
        float bv = bias[m0 + mi];
        #pragma unroll
        for (int b = 0; b < 4; b++) acc[mi][b] = bv;
    }

    #pragma unroll 2
    for (int j4 = 0; j4 < 128; ++j4) {
        float4 xv[4];
        #pragma unroll
        for (int b = 0; b < 4; b++) xv[b] = *(const float4*)&xs[b][j4 * 4];
        #pragma unroll
        for (int mi = 0; mi < 2; mi++) {
            float4 wv = *(const float4*)&W[(size_t)(m0 + mi) * 512 + j4 * 4];
            #pragma unroll
            for (int b = 0; b < 4; b++) {
                acc[mi][b] += wv.x * xv[b].x;
                acc[mi][b] += wv.y * xv[b].y;
                acc[mi][b] += wv.z * xv[b].z;
                acc[mi][b] += wv.w * xv[b].w;
            }
        }
    }

    #pragma unroll
    for (int mi = 0; mi < 2; mi++)
        #pragma unroll
        for (int b = 0; b < 4; b++)
            os[b][m0 + mi] = acc[mi][b];
    __syncthreads();

    const int wid = tid >> 5, lane = tid & 31;
    if (wid < 4) {
        const int bb = wid;
        float ss = 0.f;
        for (int j = lane; j < 512; j += 32) { float v = os[bb][j]; ss += v * v; }
        #pragma unroll
        for (int o = 16; o; o >>= 1) ss += __shfl_xor_sync(0xFFFFFFFFu, ss, o);
        float inv = 1.0f / fmaxf(sqrtf(ss), 1e-12f);
        if (mat == 0) {
            for (int j = lane; j < 512; j += 32)
                g_img[(size_t)(b0 + bb) * 512 + j] = os[bb][j] * inv;
        } else {
            for (int j = lane; j < 512; j += 32)
                g_txt_bf[(size_t)(b0 + bb) * 512 + j] = __float2bfloat16(os[bb][j] * inv);
        }
    }
}

// ===========================================================================
// Stage 2: bf16 mma.sync bilinear GEMM.
// CTA: k = bid>>2, ichunk = bid&3. Tile M=256(batch) x N=128(i), K=512(j).
// 512 threads = 16 warps: wm = w>>2 (64 batch rows), wn = w&3 (32 i cols).
// BK=32 per chunk, 16 chunks, double-buffered. smem rows padded to 80B
// (stride 80: 8-row ldmatrix groups hit 8 distinct 16B banks -> conflict-free).
// ===========================================================================

__device__ __forceinline__ uint32_t smem_u32(const void* p) {
    uint32_t a;
    asm("{ .reg .u64 t; cvta.to.shared.u64 t, %1; cvt.u32.u64 %0, t; }"
        : "=r"(a) : "l"(p));
    return a;
}

__device__ __forceinline__ void cp16(uint32_t dst, const void* src) {
    asm volatile("cp.async.cg.shared.global [%0], [%1], 16;" :: "r"(dst), "l"(src));
}

__device__ __forceinline__ void ldsm4(uint32_t& r0, uint32_t& r1,
                                      uint32_t& r2, uint32_t& r3, uint32_t addr) {
    asm volatile("ldmatrix.sync.aligned.m8n8.x4.shared.b16 {%0,%1,%2,%3}, [%4];"
                 : "=r"(r0), "=r"(r1), "=r"(r2), "=r"(r3) : "r"(addr));
}

#define TXT_B 20480   // 256 rows * 80 B
#define WP_B  10240   // 128 rows * 80 B
#define K2_SMEM (2 * TXT_B + 2 * WP_B)   // 61440

__global__ void __launch_bounds__(512, 1) bilinear_kernel(const float* __restrict__ Wp)
{
    extern __shared__ __align__(16) char dsm[];
    const uint32_t smb   = smem_u32(dsm);
    const uint32_t txtb0 = smb, txtb1 = smb + TXT_B;
    const uint32_t wpb0  = smb + 2 * TXT_B, wpb1 = wpb0 + WP_B;

    const int tid  = threadIdx.x;
    const int lane = tid & 31;
    const int w    = tid >> 5;
    const int wm   = w >> 2;      // 0..3 -> batch rows wm*64
    const int wn   = w & 3;       // 0..3 -> i cols wn*32

    const int k      = blockIdx.x >> 2;
    const int ichunk = blockIdx.x & 3;
    const float* wpk = Wp + ((size_t)k << 18) + ((size_t)ichunk << 16);

    // ---- txt (A) async loads: 256 rows x 32 bf16 per chunk ----
    auto cp_txt = [&](int jc, uint32_t base) {
        #pragma unroll
        for (int q = 0; q < 2; q++) {
            int idx = tid + 512 * q;
            int row = idx >> 2, c16 = idx & 3;
            cp16(base + (uint32_t)(row * 80 + c16 * 16),
                 g_txt_bf + (size_t)row * 512 + jc * 32 + c16 * 8);
        }
        asm volatile("cp.async.commit_group;" ::: "memory");
    };

    // ---- Wp (B): register-staged fp32 LDG -> bf16 STS ----
    const int wrow = tid >> 2, wseg = tid & 3;
    const float* wsrc = wpk + (size_t)wrow * 512 + wseg * 8;
    const uint32_t wsts = (uint32_t)(wrow * 80 + wseg * 16);
    float4 stl, sth;
    auto ldg_wp = [&](int jc) {
        const float4* p = (const float4*)(wsrc + jc * 32);
        stl = p[0]; sth = p[1];
    };
    auto sts_wp = [&](uint32_t base) {
        uint32_t p0, p1, p2, p3;
        asm("cvt.rn.bf16x2.f32 %0, %1, %2;" : "=r"(p0) : "f"(stl.y), "f"(stl.x));
        asm("cvt.rn.bf16x2.f32 %0, %1, %2;" : "=r"(p1) : "f"(stl.w), "f"(stl.z));
        asm("cvt.rn.bf16x2.f32 %0, %1, %2;" : "=r"(p2) : "f"(sth.y), "f"(sth.x));
        asm("cvt.rn.bf16x2.f32 %0, %1, %2;" : "=r"(p3) : "f"(sth.w), "f"(sth.z));
        asm volatile("st.shared.v4.b32 [%0], {%1,%2,%3,%4};"
                     :: "r"(base + wsts), "r"(p0), "r"(p1), "r"(p2), "r"(p3)
                     : "memory");
    };

    // ---- ldmatrix lane offsets ----
    const int ln = lane & 7, sel = lane >> 3;
    const int a_row = ((sel & 1) << 3) + ln, a_half = sel >> 1;
    const int b_row = ((sel >> 1) << 3) + ln, b_half = sel & 1;
    uint32_t a_off[4], b_off[2];
    #pragma unroll
    for (int mt = 0; mt < 4; mt++)
        a_off[mt] = (uint32_t)((wm * 64 + mt * 16 + a_row) * 80 + a_half * 16);
    #pragma unroll
    for (int p = 0; p < 2; p++)
        b_off[p] = (uint32_t)((wn * 32 + p * 16 + b_row) * 80 + b_half * 16);

    float d[4][4][4];
    #pragma unroll
    for (int mt = 0; mt < 4; mt++)
        #pragma unroll
        for (int nt = 0; nt < 4; nt++)
            #pragma unroll
            for (int r = 0; r < 4; r++) d[mt][nt][r] = 0.f;

    // ---- prologue ----
    ldg_wp(0);
    sts_wp(wpb0);
    cp_txt(0, txtb0);
    ldg_wp(1);

    // ---- mainloop ----
    for (int jc = 0; jc < 16; ++jc) {
        const uint32_t tb = (jc & 1) ? txtb1 : txtb0;
        const uint32_t wb = (jc & 1) ? wpb1 : wpb0;
        asm volatile("cp.async.wait_group 0;" ::: "memory");
        __syncthreads();
        if (jc < 15) cp_txt(jc + 1, (jc & 1) ? txtb0 : txtb1);

        #pragma unroll
        for (int kf = 0; kf < 2; kf++) {
            const uint32_t ko = kf * 32;
            uint32_t a[4][4], bq[2][4];
            #pragma unroll
            for (int mt = 0; mt < 4; mt++)
                ldsm4(a[mt][0], a[mt][1], a[mt][2], a[mt][3], tb + a_off[mt] + ko);
            #pragma unroll
            for (int p = 0; p < 2; p++)
                ldsm4(bq[p][0], bq[p][1], bq[p][2], bq[p][3], wb + b_off[p] + ko);
            #pragma unroll
            for (int mt = 0; mt < 4; mt++)
                #pragma unroll
                for (int nt = 0; nt < 4; nt++) {
                    const uint32_t bb0 = bq[nt >> 1][(nt & 1) * 2];
                    const uint32_t bb1 = bq[nt >> 1][(nt & 1) * 2 + 1];
                    asm volatile(
                        "mma.sync.aligned.m16n8k16.row.col.f32.bf16.bf16.f32 "
                        "{%0,%1,%2,%3},{%4,%5,%6,%7},{%8,%9},{%0,%1,%2,%3};"
                        : "+f"(d[mt][nt][0]), "+f"(d[mt][nt][1]),
                          "+f"(d[mt][nt][2]), "+f"(d[mt][nt][3])
                        : "r"(a[mt][0]), "r"(a[mt][1]), "r"(a[mt][2]), "r"(a[mt][3]),
                          "r"(bb0), "r"(bb1));
                }
        }

        if (jc < 15) {
            sts_wp((jc & 1) ? wpb0 : wpb1);
            if (jc < 14) ldg_wp(jc + 2);
        }
    }

    // ---- epilogue: feats partial = sum_i img[b,i] * D[b,i], reduce over wn ----
    __syncthreads();
    float* s_feat = (float*)dsm;
    for (int v = tid; v < 256; v += 512) s_feat[v] = 0.f;
    __syncthreads();

    const int g = lane >> 2, c = lane & 3;
    #pragma unroll
    for (int mt = 0; mt < 4; mt++) {
        const int b_lo = wm * 64 + mt * 16 + g;
        const int b_hi = b_lo + 8;
        float plo = 0.f, phi = 0.f;
        #pragma unroll
        for (int nt = 0; nt < 4; nt++) {
            const int icol = ichunk * 128 + wn * 32 + nt * 8 + 2 * c;
            float2 vlo = *(const float2*)&g_img[((size_t)b_lo << 9) + icol];
            float2 vhi = *(const float2*)&g_img[((size_t)b_hi << 9) + icol];
            plo += d[mt][nt][0] * vlo.x + d[mt][nt][1] * vlo.y;
            phi += d[mt][nt][2] * vhi.x + d[mt][nt][3] * vhi.y;
        }
        plo += __shfl_xor_sync(0xFFFFFFFFu, plo, 1);
        plo += __shfl_xor_sync(0xFFFFFFFFu, plo, 2);
        phi += __shfl_xor_sync(0xFFFFFFFFu, phi, 1);
        phi += __shfl_xor_sync(0xFFFFFFFFu, phi, 2);
        if (c == 0) {
            atomicAdd(&s_feat[b_lo], plo);
            atomicAdd(&s_feat[b_hi], phi);
        }
    }
    __syncthreads();
    if (tid < 256)
        g_part[(size_t)tid * 2048 + k * 4 + ichunk] = s_feat[tid];
}

// ===========================================================================
// Stage 3: out[b] = sigmoid( sum_k relu(sum_s part + bp[k]) * Wc[k] + bc )
// ===========================================================================
__global__ void __launch_bounds__(128) head_kernel(
    const float* __restrict__ bp, const float* __restrict__ Wc,
    const float* __restrict__ bc, float* __restrict__ out)
{
    const int b = blockIdx.x;
    const int t = threadIdx.x;
    float s = 0.f;
    for (int k = t; k < 512; k += 128) {
        float4 v = *(const float4*)&g_part[(size_t)b * 2048 + k * 4];
        float f = bp[k] + v.x + v.y + v.z + v.w;
        s += fmaxf(f, 0.f) * Wc[k];
    }
    #pragma unroll
    for (int o = 16; o; o >>= 1) s += __shfl_xor_sync(0xFFFFFFFFu, s, o);
    __shared__ float red[4];
    if ((t & 31) == 0) red[t >> 5] = s;
    __syncthreads();
    if (t == 0) {
        float tot = red[0] + red[1] + red[2] + red[3] + bc[0];
        out[b] = 1.f / (1.f + expf(-tot));
    }
}

// ===========================================================================
extern "C" void kernel_launch(void* const* d_in, const int* in_sizes, int n_in,
                              void* d_out, int out_size)
{
    const float* img_e = (const float*)d_in[0];
    const float* txt_e = (const float*)d_in[1];
    const float* Wi    = (const float*)d_in[2];
    const float* bi    = (const float*)d_in[3];
    const float* Wt    = (const float*)d_in[4];
    const float* bt    = (const float*)d_in[5];
    const float* Wp    = (const float*)d_in[6];
    const float* bp    = (const float*)d_in[7];
    const float* Wc    = (const float*)d_in[8];
    const float* bc    = (const float*)d_in[9];
    float* out = (float*)d_out;

    cudaFuncSetAttribute(bilinear_kernel,
                         cudaFuncAttributeMaxDynamicSharedMemorySize, K2_SMEM);

    map_norm_kernel<<<128, 256>>>(img_e, txt_e, Wi, bi, Wt, bt);
    bilinear_kernel<<<2048, 512, K2_SMEM>>>(Wp);
    head_kernel<<<256, 128>>>(bp, Wc, bc, out);
}